// round 8
// baseline (speedup 1.0000x reference)
#include <cuda_runtime.h>

#define DIM (1u<<22)
#define NT 1024
#define GRID 444
typedef unsigned long long ull;

// Persistent scratch (allowed: __device__ globals, no allocation)
__device__ ull g_bufA[DIM];                 // packed (re,im) amplitudes
__device__ ull g_bufB[DIM];
__device__ __align__(16) ull g_Upk[4*22*8]; // per gate: 8 packed-broadcast consts
__device__ double g_acc[23];                // z[0..21], total at [22]

__device__ __forceinline__ int SWZ(int a){ return a ^ ((a>>4)&15); }

__device__ __forceinline__ ull fma2(ull a, ull b, ull c){
  ull d; asm("fma.rn.f32x2 %0, %1, %2, %3;" : "=l"(d) : "l"(a), "l"(b), "l"(c)); return d;
}
__device__ __forceinline__ ull mul2(ull a, ull b){
  ull d; asm("mul.rn.f32x2 %0, %1, %2;" : "=l"(d) : "l"(a), "l"(b)); return d;
}
__device__ __forceinline__ ull swp(ull a){ return (a>>32)|(a<<32); }
__device__ __forceinline__ ull packf(float lo, float hi){
  return (ull)__float_as_uint(lo) | ((ull)__float_as_uint(hi)<<32);
}
__device__ __forceinline__ void cpa16(unsigned d, const void* s){
  asm volatile("cp.async.cg.shared.global [%0], [%1], 16;" :: "r"(d), "l"(s) : "memory");
}
#define CP_COMMIT() asm volatile("cp.async.commit_group;" ::: "memory")
#define CP_WAIT0()  asm volatile("cp.async.wait_group 0;" ::: "memory")

__device__ __forceinline__ float2 cxmul(float2 a, float2 b){
  return make_float2(a.x*b.x - a.y*b.y, a.x*b.y + a.y*b.x);
}

// Apply 2x2 gate on register-bit J over 16 register-resident packed amps.
template<int J>
__device__ __forceinline__ void gate16(ull (&r)[16], const ull* __restrict__ Up){
  const ulonglong2 q0 = ((const ulonglong2*)Up)[0];
  const ulonglong2 q1 = ((const ulonglong2*)Up)[1];
  const ulonglong2 q2 = ((const ulonglong2*)Up)[2];
  const ulonglong2 q3 = ((const ulonglong2*)Up)[3];
  const ull c00=q0.x, d00=q0.y, c01=q1.x, d01=q1.y;
  const ull c10=q2.x, d10=q2.y, c11=q3.x, d11=q3.y;
#pragma unroll
  for (int i=0;i<16;i++){
    if ((i & (1<<J)) == 0){
      const int j2 = i | (1<<J);
      const ull a=r[i], b=r[j2], as=swp(a), bs=swp(b);
      r[i]  = fma2(c00,a, fma2(d00,as, fma2(c01,b, mul2(d01,bs))));
      r[j2] = fma2(c10,a, fma2(d10,as, fma2(c11,b, mul2(d11,bs))));
    }
  }
}

// ---------------------------------------------------------------------------
__global__ void k_prep(const float* __restrict__ params){
  int i = threadIdx.x;
  if (i < 23) g_acc[i] = 0.0;
  if (i < 88){
    float tx = 0.5f*params[i*3+0];
    float ty = 0.5f*params[i*3+1];
    float tz = 0.5f*params[i*3+2];
    float cx,sx,cy,sy,cz,sz;
    sincosf(tx,&sx,&cx); sincosf(ty,&sy,&cy); sincosf(tz,&sz,&cz);
    float2 M00 = make_float2( cy*cx,  sy*sx);
    float2 M01 = make_float2(-sy*cx, -cy*sx);
    float2 M10 = make_float2( sy*cx, -cy*sx);
    float2 M11 = make_float2( cy*cx, -sy*sx);
    float2 em = make_float2(cz,-sz), ep = make_float2(cz,sz);
    float2 U00=cxmul(em,M00), U01=cxmul(em,M01);
    float2 U10=cxmul(ep,M10), U11=cxmul(ep,M11);
    ull* Up = &g_Upk[i*8];
    Up[0]=packf(U00.x,U00.x); Up[1]=packf(-U00.y,U00.y);
    Up[2]=packf(U01.x,U01.x); Up[3]=packf(-U01.y,U01.y);
    Up[4]=packf(U10.x,U10.x); Up[5]=packf(-U10.y,U10.y);
    Up[6]=packf(U11.x,U11.x); Up[7]=packf(-U11.y,U11.y);
  }
}

// ---------------------------------------------------------------------------
// Prefetch helpers: bulk-copy one tile into smem via cp.async.
// passA non-first: source of the Gray gather for dest tile `tile` is the
// CONTIGUOUS block S = tile ^ (tile>>1) (x's bits>=12 are constant).
// ---------------------------------------------------------------------------
template<bool FIRST>
__device__ __forceinline__ void prefA(unsigned sbuf, int tile,
                                      const ull* in, const float* sre,
                                      const float* sim, int t){
  if (FIRST){
    const char* s0 = (const char*)(sre + ((size_t)tile<<12));
    const char* s1 = (const char*)(sim + ((size_t)tile<<12));
#pragma unroll
    for (int k=0;k<4;k++){
      unsigned o = (unsigned)(k*256+t)<<4;
      cpa16(sbuf + o,         s0 + o);
      cpa16(sbuf + 16384 + o, s1 + o);
    }
  } else {
    int S = tile ^ (tile>>1);
    const char* s = (const char*)(in + ((size_t)S<<12));
#pragma unroll
    for (int k=0;k<8;k++){
      unsigned o = (unsigned)(k*256+t)<<4;
      cpa16(sbuf + o, s + o);
    }
  }
}

// passB: tile gathers 1024 groups of 4 contiguous ull (32B) strided 32KB.
__device__ __forceinline__ void prefB(unsigned sbuf, int tile,
                                      const ull* buf, int t){
  const char* s = (const char*)buf;
#pragma unroll
  for (int k=0;k<4;k++){
    size_t c = (size_t)(t + 256*k);
    size_t go = (c<<15) + ((size_t)(unsigned)tile<<5);
    unsigned dz = (unsigned)(c<<5);
    cpa16(sbuf + dz,      s + go);
    cpa16(sbuf + dz + 16, s + go + 16);
  }
}

// ---------------------------------------------------------------------------
// Pass A (persistent, double-buffered): gates on global bits 0..11
// (qubits 21..10). Per tile: load M1 (from smem, Gray-permuted read for
// layers>=2), stages M1 -> M2 -> M0, store M0. Exchange scratch reuses the
// current tile buffer (sync2 protects cross-region reads).
//   M0: a=(v<<8)|t   M1: a=((t>>4)<<8)|(v<<4)|(t&15)   M2: a=(t<<4)|v
// ---------------------------------------------------------------------------
template<bool FIRST>
__global__ void __launch_bounds__(256,3) k_passA(
    const float* __restrict__ sre, const float* __restrict__ sim,
    int layer, int dir)
{
  extern __shared__ ull dsm[];                 // 2 x 4096 ull (64KB)
  __shared__ __align__(16) ull shU[96];        // M1(q17..14), M2(q21..18), M0(q13..10)
  const int t = threadIdx.x;
  const ull* in  = dir ? g_bufB : g_bufA;
  ull*       out = dir ? g_bufA : g_bufB;
  const ull* Ub = &g_Upk[layer*176];

  // per-warp duplicated const staging (identical writes; published by sync1)
  {
    const int l = (t & 31) * 3;
    const int qmapA[12] = {17,16,15,14, 21,20,19,18, 13,12,11,10};
    if (l   < 96) shU[l]   = Ub[qmapA[l>>3]*8 + (l&7)];
    if (l+1 < 96) shU[l+1] = Ub[qmapA[(l+1)>>3]*8 + ((l+1)&7)];
    if (l+2 < 96) shU[l+2] = Ub[qmapA[(l+2)>>3]*8 + ((l+2)&7)];
  }

  unsigned sb = (unsigned)__cvta_generic_to_shared(dsm);
  int tile = blockIdx.x;
  prefA<FIRST>(sb, tile, in, sre, sim, t);
  CP_COMMIT();
  int cur = 0;
  const unsigned aM1b = (((unsigned)t>>4)<<8) | ((unsigned)t&15);

  while (tile < NT){
    CP_WAIT0();
    __syncthreads();                           // sync1: tile data visible, prev iter done
    int nt2 = tile + GRID;
    if (nt2 < NT){
      prefA<FIRST>(sb + ((unsigned)(cur^1)<<15), nt2, in, sre, sim, t);
      CP_COMMIT();
    }
    ull* sm = dsm + (cur<<12);
    ull r[16];
    if (FIRST){
      const float* fb = (const float*)sm;
#pragma unroll
      for (int v=0;v<16;v++){
        unsigned a = aM1b | ((unsigned)v<<4);
        r[v] = packf(fb[a], fb[4096+a]);
      }
    } else {
      const unsigned gfix = ((unsigned)tile&1)<<11;
#pragma unroll
      for (int v=0;v<16;v++){
        unsigned a = aM1b | ((unsigned)v<<4);
        unsigned xl = (a ^ (a>>1)) ^ gfix;     // Gray-gather local index
        r[v] = sm[xl];
      }
    }
    __syncthreads();                           // sync2: all reads done before scratch reuse
    // stage M1: reg bit j -> a bit 4+j -> qubit 17-j
    gate16<0>(r, shU + 0);
    gate16<1>(r, shU + 8);
    gate16<2>(r, shU + 16);
    gate16<3>(r, shU + 24);
    // exchange M1 -> M2 (half-warp local)
#pragma unroll
    for (int v=0;v<16;v++) sm[SWZ(aM1b | (v<<4))] = r[v];
    __syncwarp();
#pragma unroll
    for (int v=0;v<16;v++) r[v] = sm[SWZ((t<<4)|v)];
    // stage M2: reg bit j -> a bit j -> qubit 21-j
    gate16<0>(r, shU + 32);
    gate16<1>(r, shU + 40);
    gate16<2>(r, shU + 48);
    gate16<3>(r, shU + 56);
    // exchange M2 -> M0 (block-wide)
#pragma unroll
    for (int v=0;v<16;v++) sm[SWZ((t<<4)|v)] = r[v];
    __syncthreads();                           // sync3
#pragma unroll
    for (int v=0;v<16;v++) r[v] = sm[SWZ((v<<8)|t)];
    // stage M0: reg bit j -> a bit 8+j -> qubit 13-j
    gate16<0>(r, shU + 64);
    gate16<1>(r, shU + 72);
    gate16<2>(r, shU + 80);
    gate16<3>(r, shU + 88);
    // store (coalesced)
#pragma unroll
    for (int v=0;v<16;v++) out[((unsigned)tile<<12) | ((unsigned)v<<8) | (unsigned)t] = r[v];
    cur ^= 1;
    tile = nt2;
  }
}

// ---------------------------------------------------------------------------
// Pass B (persistent, double-buffered): gates on global bits 12..21
// (qubits 9..0). In-place; tile j's read set == write set == region j, so
// pipeline prefetch never races other tiles' stores.
// ---------------------------------------------------------------------------
__global__ void __launch_bounds__(256,3) k_passB(int layer, int sel)
{
  extern __shared__ ull dsm[];
  __shared__ __align__(16) ull shU[80];        // M1(q7..4), M2(q9,q8), M0(q3..0)
  const int t = threadIdx.x;
  ull* buf = sel ? g_bufA : g_bufB;
  const ull* Ub = &g_Upk[layer*176];

  {
    const int l = (t & 31) * 3;
    const int qmapB[10] = {7,6,5,4, 9,8, 3,2,1,0};
    if (l   < 80) shU[l]   = Ub[qmapB[l>>3]*8 + (l&7)];
    if (l+1 < 80) shU[l+1] = Ub[qmapB[(l+1)>>3]*8 + ((l+1)&7)];
    if (l+2 < 80) shU[l+2] = Ub[qmapB[(l+2)>>3]*8 + ((l+2)&7)];
  }

  unsigned sb = (unsigned)__cvta_generic_to_shared(dsm);
  int tile = blockIdx.x;
  prefB(sb, tile, buf, t);
  CP_COMMIT();
  int cur = 0;
  const unsigned aM1b = (((unsigned)t>>4)<<8) | ((unsigned)t&15);

  while (tile < NT){
    CP_WAIT0();
    __syncthreads();                           // sync1
    int nt2 = tile + GRID;
    if (nt2 < NT){
      prefB(sb + ((unsigned)(cur^1)<<15), nt2, buf, t);
      CP_COMMIT();
    }
    ull* sm = dsm + (cur<<12);
    ull r[16];
#pragma unroll
    for (int v=0;v<16;v++) r[v] = sm[aM1b | ((unsigned)v<<4)];
    // plain layout: each half-warp reads only its own region -> no sync2 needed
    // stage M1: qubit 7-j
    gate16<0>(r, shU + 0);
    gate16<1>(r, shU + 8);
    gate16<2>(r, shU + 16);
    gate16<3>(r, shU + 24);
#pragma unroll
    for (int v=0;v<16;v++) sm[SWZ(aM1b | (v<<4))] = r[v];
    __syncwarp();
#pragma unroll
    for (int v=0;v<16;v++) r[v] = sm[SWZ((t<<4)|v)];
    // stage M2: qubits 9,8
    gate16<2>(r, shU + 32);
    gate16<3>(r, shU + 40);
#pragma unroll
    for (int v=0;v<16;v++) sm[SWZ((t<<4)|v)] = r[v];
    __syncthreads();                           // sync3
#pragma unroll
    for (int v=0;v<16;v++) r[v] = sm[SWZ((v<<8)|t)];
    // stage M0: qubit 3-j
    gate16<0>(r, shU + 48);
    gate16<1>(r, shU + 56);
    gate16<2>(r, shU + 64);
    gate16<3>(r, shU + 72);
    const unsigned gbase0 = (((unsigned)t>>2)<<12) | ((unsigned)tile<<2) | ((unsigned)t&3);
#pragma unroll
    for (int v=0;v<16;v++) buf[gbase0 | ((unsigned)v<<18)] = r[v];
    cur ^= 1;
    tile = nt2;
  }
}

// ---------------------------------------------------------------------------
// Pass B (last): non-persistent (runs once). Gate structure + fused final
// CNOT ladder + <Z_q> reduction (no final state store).
// ---------------------------------------------------------------------------
__global__ void __launch_bounds__(256,3) k_passB_last(int layer, int sel)
{
  __shared__ ull sh[4096];
  __shared__ __align__(16) ull shU[80];
  __shared__ double sacc[23];
  const int t = threadIdx.x;
  const unsigned blk = blockIdx.x;
  ull* buf = sel ? g_bufA : g_bufB;
  const ull* Ub = &g_Upk[layer*176];
  ull r[16];

  const unsigned aM1b = (((unsigned)t>>4)<<8) | ((unsigned)t&15);
#pragma unroll
  for (int v=0;v<16;v++){
    unsigned a = aM1b | ((unsigned)v<<4);
    unsigned g = ((a>>2)<<12) | (blk<<2) | (a&3);
    r[v] = buf[g];
  }
  {
    const int l = (t & 31) * 3;
    const int qmapB[10] = {7,6,5,4, 9,8, 3,2,1,0};
    if (l   < 80) shU[l]   = Ub[qmapB[l>>3]*8 + (l&7)];
    if (l+1 < 80) shU[l+1] = Ub[qmapB[(l+1)>>3]*8 + ((l+1)&7)];
    if (l+2 < 80) shU[l+2] = Ub[qmapB[(l+2)>>3]*8 + ((l+2)&7)];
  }
  if (t < 23) sacc[t] = 0.0;
  __syncwarp();

  gate16<0>(r, shU + 0);
  gate16<1>(r, shU + 8);
  gate16<2>(r, shU + 16);
  gate16<3>(r, shU + 24);
#pragma unroll
  for (int v=0;v<16;v++) sh[SWZ(aM1b | (v<<4))] = r[v];
  __syncwarp();
#pragma unroll
  for (int v=0;v<16;v++) r[v] = sh[SWZ((t<<4)|v)];
  gate16<2>(r, shU + 32);
  gate16<3>(r, shU + 40);
#pragma unroll
  for (int v=0;v<16;v++) sh[SWZ((t<<4)|v)] = r[v];
  __syncthreads();
#pragma unroll
  for (int v=0;v<16;v++) r[v] = sh[SWZ((v<<8)|t)];
  gate16<0>(r, shU + 48);
  gate16<1>(r, shU + 56);
  gate16<2>(r, shU + 64);
  gate16<3>(r, shU + 72);

  const unsigned gbase0 = (((unsigned)t>>2)<<12) | (blk<<2) | ((unsigned)t&3);
  float z[22];
#pragma unroll
  for (int q=0;q<22;q++) z[q] = 0.0f;
  float tot = 0.0f;
#pragma unroll
  for (int v=0;v<16;v++){
    unsigned g = gbase0 | ((unsigned)v<<18);
    unsigned y = g; y ^= y>>1; y ^= y>>2; y ^= y>>4; y ^= y>>8; y ^= y>>16;
    float re = __uint_as_float((unsigned)r[v]);
    float im = __uint_as_float((unsigned)(r[v]>>32));
    float p = re*re + im*im;
    tot += p;
#pragma unroll
    for (int q=0;q<22;q++)
      z[q] += ((y >> (21-q)) & 1u) ? -p : p;
  }
#pragma unroll
  for (int q=0;q<22;q++){
    float val = z[q];
#pragma unroll
    for (int o=16;o;o>>=1) val += __shfl_down_sync(0xffffffffu, val, o);
    if ((t & 31) == 0) atomicAdd(&sacc[q], (double)val);
  }
  {
    float val = tot;
#pragma unroll
    for (int o=16;o;o>>=1) val += __shfl_down_sync(0xffffffffu, val, o);
    if ((t & 31) == 0) atomicAdd(&sacc[22], (double)val);
  }
  __syncthreads();
  if (t < 23) atomicAdd(&g_acc[t], sacc[t]);
}

__global__ void k_final(float* __restrict__ out){
  int q = threadIdx.x;
  if (q < 22) out[q] = (float)(g_acc[q] / g_acc[22]);
}

extern "C" void kernel_launch(void* const* d_in, const int* in_sizes, int n_in,
                              void* d_out, int out_size)
{
  const float* params = (const float*)d_in[0];
  const float* sre    = (const float*)d_in[1];
  const float* sim    = (const float*)d_in[2];
  float* out = (float*)d_out;

  const int DSM = 65536;
  cudaFuncSetAttribute(k_passA<true>,  cudaFuncAttributeMaxDynamicSharedMemorySize, DSM);
  cudaFuncSetAttribute(k_passA<false>, cudaFuncAttributeMaxDynamicSharedMemorySize, DSM);
  cudaFuncSetAttribute(k_passB,        cudaFuncAttributeMaxDynamicSharedMemorySize, DSM);

  k_prep<<<1,128>>>(params);

  // Layer 1: A writes bufA (dir=1), B in-place on bufA (sel=1)
  k_passA<true ><<<GRID,256,DSM>>>(sre, sim, 0, 1);
  k_passB<<<GRID,256,DSM>>>(0, 1);
  // Layer 2: bufA -> bufB (dir=0), B on bufB (sel=0)
  k_passA<false><<<GRID,256,DSM>>>(nullptr, nullptr, 1, 0);
  k_passB<<<GRID,256,DSM>>>(1, 0);
  // Layer 3: bufB -> bufA
  k_passA<false><<<GRID,256,DSM>>>(nullptr, nullptr, 2, 1);
  k_passB<<<GRID,256,DSM>>>(2, 1);
  // Layer 4: bufA -> bufB, B fuses final ladder + reduction
  k_passA<false><<<GRID,256,DSM>>>(nullptr, nullptr, 3, 0);
  k_passB_last<<<1024,256>>>(3, 0);

  k_final<<<1,32>>>(out);
}

// round 11
// speedup vs baseline: 1.1903x; 1.1903x over previous
#include <cuda_runtime.h>

#define DIM (1u<<22)
typedef unsigned long long ull;

// Persistent scratch (allowed: __device__ globals, no allocation)
__device__ ull g_bufA[DIM];                 // packed (re,im) amplitudes
__device__ ull g_bufB[DIM];
__device__ double g_acc[23];                // z[0..21], total at [22]

__device__ __forceinline__ int SWZ(int a){ return a ^ ((a>>4)&15); }

__device__ __forceinline__ ull fma2(ull a, ull b, ull c){
  ull d; asm("fma.rn.f32x2 %0, %1, %2, %3;" : "=l"(d) : "l"(a), "l"(b), "l"(c)); return d;
}
__device__ __forceinline__ ull mul2(ull a, ull b){
  ull d; asm("mul.rn.f32x2 %0, %1, %2;" : "=l"(d) : "l"(a), "l"(b)); return d;
}
__device__ __forceinline__ ull swp(ull a){ return (a>>32)|(a<<32); }
__device__ __forceinline__ ull packf(float lo, float hi){
  return (ull)__float_as_uint(lo) | ((ull)__float_as_uint(hi)<<32);
}
__device__ __forceinline__ float2 cxmul(float2 a, float2 b){
  return make_float2(a.x*b.x - a.y*b.y, a.x*b.y + a.y*b.x);
}

// Compute fused gate U = RZ*RY*RX for (layer, qubit) and write the 8
// packed-broadcast constants to dst[0..7]. Pure function of params ->
// bit-identical across all redundant computations (benign duplicated writes).
__device__ __forceinline__ void make_gate(const float* __restrict__ params,
                                          int layer, int q, ull* dst){
  const float* p = params + (layer*22 + q)*3;
  float tx = 0.5f*p[0], ty = 0.5f*p[1], tz = 0.5f*p[2];
  float cx,sx,cy,sy,cz,sz;
  sincosf(tx,&sx,&cx); sincosf(ty,&sy,&cy); sincosf(tz,&sz,&cz);
  // M = RY*RX
  float2 M00 = make_float2( cy*cx,  sy*sx);
  float2 M01 = make_float2(-sy*cx, -cy*sx);
  float2 M10 = make_float2( sy*cx, -cy*sx);
  float2 M11 = make_float2( cy*cx, -sy*sx);
  float2 em = make_float2(cz,-sz), ep = make_float2(cz,sz); // e^{-itz}, e^{+itz}
  float2 U00=cxmul(em,M00), U01=cxmul(em,M01);
  float2 U10=cxmul(ep,M10), U11=cxmul(ep,M11);
  dst[0]=packf(U00.x,U00.x); dst[1]=packf(-U00.y,U00.y);
  dst[2]=packf(U01.x,U01.x); dst[3]=packf(-U01.y,U01.y);
  dst[4]=packf(U10.x,U10.x); dst[5]=packf(-U10.y,U10.y);
  dst[6]=packf(U11.x,U11.x); dst[7]=packf(-U11.y,U11.y);
}

// Apply 2x2 gate on register-bit J over 16 register-resident packed amps.
// Complex update via packed f32x2: res = (u.x,u.x)*a + (-u.y,u.y)*swap(a) + ...
template<int J>
__device__ __forceinline__ void gate16(ull (&r)[16], const ull* __restrict__ Up){
  const ulonglong2 q0 = ((const ulonglong2*)Up)[0];
  const ulonglong2 q1 = ((const ulonglong2*)Up)[1];
  const ulonglong2 q2 = ((const ulonglong2*)Up)[2];
  const ulonglong2 q3 = ((const ulonglong2*)Up)[3];
  const ull c00=q0.x, d00=q0.y, c01=q1.x, d01=q1.y;
  const ull c10=q2.x, d10=q2.y, c11=q3.x, d11=q3.y;
#pragma unroll
  for (int i=0;i<16;i++){
    if ((i & (1<<J)) == 0){
      const int j2 = i | (1<<J);
      const ull a=r[i], b=r[j2], as=swp(a), bs=swp(b);
      r[i]  = fma2(c00,a, fma2(d00,as, fma2(c01,b, mul2(d01,bs))));
      r[j2] = fma2(c10,a, fma2(d10,as, fma2(c11,b, mul2(d11,bs))));
    }
  }
}

// ---------------------------------------------------------------------------
// Pass A: gates on global bits 0..11 (qubits 21..10). Tile = 4096 contiguous.
// 2-exchange structure; exchange M1->M2 is 16-thread (half-warp) local ->
// __syncwarp; only M2->M0 needs a block barrier.
// Gates computed in-kernel: lanes 0..11 of EVERY warp redundantly compute all
// 12 fused matrices and write identical values to shU (benign races),
// published warp-locally by the first __syncwarp.
//   M0: a=(v<<8)|t   M1: a=((t>>4)<<8)|(v<<4)|(t&15)   M2: a=(t<<4)|v
// Layers >= 2 fuse prior layer's CNOT ladder as Gray-code gather in[y^(y>>1)].
// FIRST also zeroes g_acc (block 0) - stream-ordered before k_passB_last.
// ---------------------------------------------------------------------------
template<bool FIRST>
__global__ void __launch_bounds__(256,3) k_passA(
    const float* __restrict__ params,
    const float* __restrict__ sre, const float* __restrict__ sim,
    int layer, int dir)
{
  __shared__ ull sh[4096];
  __shared__ __align__(16) ull shU[96];   // M1(q17..14), M2(q21..18), M0(q13..10)
  const int t = threadIdx.x;
  const unsigned base = (unsigned)blockIdx.x << 12;
  const ull* in  = dir ? g_bufB : g_bufA;
  ull*       out = dir ? g_bufA : g_bufB;
  ull r[16];

  if (FIRST){
    if (blockIdx.x == 0 && t < 23) g_acc[t] = 0.0;
  }

  // amp loads first (max LDG overlap with gate computation below)
  const unsigned aM1b = (((unsigned)t>>4)<<8) | ((unsigned)t&15);
  if (FIRST){
#pragma unroll
    for (int v=0;v<16;v++){
      unsigned y = base | aM1b | ((unsigned)v<<4);
      r[v] = packf(sre[y], sim[y]);
    }
  } else {
#pragma unroll
    for (int v=0;v<16;v++){
      unsigned y = base | aM1b | ((unsigned)v<<4);
      unsigned x = y ^ (y>>1);          // inverse of CNOT-ladder permutation
      r[v] = in[x];
    }
  }
  // in-kernel gate computation, duplicated per warp (identical values)
  {
    const int l = t & 31;
    if (l < 12){
      const int qmapA[12] = {17,16,15,14, 21,20,19,18, 13,12,11,10};
      make_gate(params, layer, qmapA[l], &shU[l*8]);
    }
  }
  __syncwarp();   // publish shU within this warp (other warps wrote same bits)

  // stage M1: reg bit j -> a bit 4+j -> qubit 17-j
  gate16<0>(r, shU + 0);
  gate16<1>(r, shU + 8);
  gate16<2>(r, shU + 16);
  gate16<3>(r, shU + 24);
  // exchange M1 -> M2: half-warp local (amp bits 8..11 fixed at t>>4)
#pragma unroll
  for (int v=0;v<16;v++) sh[SWZ(aM1b | (v<<4))] = r[v];
  __syncwarp();
#pragma unroll
  for (int v=0;v<16;v++) r[v] = sh[SWZ((t<<4)|v)];
  // stage M2: reg bit j -> a bit j -> qubit 21-j
  gate16<0>(r, shU + 32);
  gate16<1>(r, shU + 40);
  gate16<2>(r, shU + 48);
  gate16<3>(r, shU + 56);
  // exchange M2 -> M0: block-wide (the single full barrier of the pass)
#pragma unroll
  for (int v=0;v<16;v++) sh[SWZ((t<<4)|v)] = r[v];
  __syncthreads();
#pragma unroll
  for (int v=0;v<16;v++) r[v] = sh[SWZ((v<<8)|t)];
  // stage M0: reg bit j -> a bit 8+j -> qubit 13-j
  gate16<0>(r, shU + 64);
  gate16<1>(r, shU + 72);
  gate16<2>(r, shU + 80);
  gate16<3>(r, shU + 88);
  // store in M0: coalesced
#pragma unroll
  for (int v=0;v<16;v++) out[base | ((unsigned)v<<8) | (unsigned)t] = r[v];
}

// ---------------------------------------------------------------------------
// Pass B (non-last): gates on global bits 12..21 (qubits 9..0). In-place.
// Tile local a (12b): a bits 0..1 = global bits 0..1 (payload),
// a bit k (k>=2) = global bit 10+k.  g = ((a>>2)<<12)|(blk<<2)|(a&3).
// Same barrier structure: per-warp duplicated gate computation + syncwarp,
// local exchange M1->M2 (syncwarp), one full barrier at M2->M0.
// ---------------------------------------------------------------------------
__global__ void __launch_bounds__(256,4) k_passB(
    const float* __restrict__ params, int layer, int sel)
{
  __shared__ ull sh[4096];
  __shared__ __align__(16) ull shU[80];   // M1(q7..4), M2(q9,q8), M0(q3..0)
  const int t = threadIdx.x;
  const unsigned blk = blockIdx.x;
  ull* buf = sel ? g_bufA : g_bufB;
  ull r[16];

  // amp loads first
  const unsigned aM1b = (((unsigned)t>>4)<<8) | ((unsigned)t&15);
#pragma unroll
  for (int v=0;v<16;v++){
    unsigned a = aM1b | ((unsigned)v<<4);
    unsigned g = ((a>>2)<<12) | (blk<<2) | (a&3);
    r[v] = buf[g];
  }
  // in-kernel gate computation, duplicated per warp
  {
    const int l = t & 31;
    if (l < 10){
      const int qmapB[10] = {7,6,5,4, 9,8, 3,2,1,0};
      make_gate(params, layer, qmapB[l], &shU[l*8]);
    }
  }
  __syncwarp();

  // stage M1: reg bit j -> a bit 4+j -> global bit 14+j -> qubit 7-j
  gate16<0>(r, shU + 0);
  gate16<1>(r, shU + 8);
  gate16<2>(r, shU + 16);
  gate16<3>(r, shU + 24);
  // exchange M1 -> M2: half-warp local
#pragma unroll
  for (int v=0;v<16;v++) sh[SWZ(aM1b | (v<<4))] = r[v];
  __syncwarp();
#pragma unroll
  for (int v=0;v<16;v++) r[v] = sh[SWZ((t<<4)|v)];
  // stage M2: reg bits 2,3 -> a bits 2,3 -> global 12,13 -> qubits 9,8
  gate16<2>(r, shU + 32);
  gate16<3>(r, shU + 40);
  // exchange M2 -> M0: block-wide (single full barrier)
#pragma unroll
  for (int v=0;v<16;v++) sh[SWZ((t<<4)|v)] = r[v];
  __syncthreads();
#pragma unroll
  for (int v=0;v<16;v++) r[v] = sh[SWZ((v<<8)|t)];
  // stage M0: reg bit j -> a bit 8+j -> global bit 18+j -> qubit 3-j
  gate16<0>(r, shU + 48);
  gate16<1>(r, shU + 56);
  gate16<2>(r, shU + 64);
  gate16<3>(r, shU + 72);

  // M0 store: a=(v<<8)|t -> g = (v<<18)|((t>>2)<<12)|(blk<<2)|(t&3)
  const unsigned gbase0 = (((unsigned)t>>2)<<12) | (blk<<2) | ((unsigned)t&3);
#pragma unroll
  for (int v=0;v<16;v++) buf[gbase0 | ((unsigned)v<<18)] = r[v];
}

// ---------------------------------------------------------------------------
// Pass B (last): same gate structure, then fused final CNOT ladder + <Z_q>
// reduction (no final state store). Needs 22 accumulator regs -> 3 CTAs/SM.
// ---------------------------------------------------------------------------
__global__ void __launch_bounds__(256,3) k_passB_last(
    const float* __restrict__ params, int layer, int sel)
{
  __shared__ ull sh[4096];
  __shared__ __align__(16) ull shU[80];
  __shared__ double sacc[23];
  const int t = threadIdx.x;
  const unsigned blk = blockIdx.x;
  ull* buf = sel ? g_bufA : g_bufB;
  ull r[16];

  const unsigned aM1b = (((unsigned)t>>4)<<8) | ((unsigned)t&15);
#pragma unroll
  for (int v=0;v<16;v++){
    unsigned a = aM1b | ((unsigned)v<<4);
    unsigned g = ((a>>2)<<12) | (blk<<2) | (a&3);
    r[v] = buf[g];
  }
  {
    const int l = t & 31;
    if (l < 10){
      const int qmapB[10] = {7,6,5,4, 9,8, 3,2,1,0};
      make_gate(params, layer, qmapB[l], &shU[l*8]);
    }
  }
  if (t < 23) sacc[t] = 0.0;   // ordered before use by the M2->M0 syncthreads
  __syncwarp();

  gate16<0>(r, shU + 0);
  gate16<1>(r, shU + 8);
  gate16<2>(r, shU + 16);
  gate16<3>(r, shU + 24);
#pragma unroll
  for (int v=0;v<16;v++) sh[SWZ(aM1b | (v<<4))] = r[v];
  __syncwarp();
#pragma unroll
  for (int v=0;v<16;v++) r[v] = sh[SWZ((t<<4)|v)];
  gate16<2>(r, shU + 32);
  gate16<3>(r, shU + 40);
#pragma unroll
  for (int v=0;v<16;v++) sh[SWZ((t<<4)|v)] = r[v];
  __syncthreads();
#pragma unroll
  for (int v=0;v<16;v++) r[v] = sh[SWZ((v<<8)|t)];
  gate16<0>(r, shU + 48);
  gate16<1>(r, shU + 56);
  gate16<2>(r, shU + 64);
  gate16<3>(r, shU + 72);

  // Fused final CNOT ladder + <Z_q> reduction.
  // r[v] lives at g = (v<<18)|((t>>2)<<12)|(blk<<2)|(t&3) (mapping M0);
  // post-ladder basis label y_p = XOR of g bits p..21 (prefix-xor).
  const unsigned gbase0 = (((unsigned)t>>2)<<12) | (blk<<2) | ((unsigned)t&3);
  float z[22];
#pragma unroll
  for (int q=0;q<22;q++) z[q] = 0.0f;
  float tot = 0.0f;
#pragma unroll
  for (int v=0;v<16;v++){
    unsigned g = gbase0 | ((unsigned)v<<18);
    unsigned y = g; y ^= y>>1; y ^= y>>2; y ^= y>>4; y ^= y>>8; y ^= y>>16;
    float re = __uint_as_float((unsigned)r[v]);
    float im = __uint_as_float((unsigned)(r[v]>>32));
    float p = re*re + im*im;
    tot += p;
#pragma unroll
    for (int q=0;q<22;q++)
      z[q] += ((y >> (21-q)) & 1u) ? -p : p;
  }
#pragma unroll
  for (int q=0;q<22;q++){
    float val = z[q];
#pragma unroll
    for (int o=16;o;o>>=1) val += __shfl_down_sync(0xffffffffu, val, o);
    if ((t & 31) == 0) atomicAdd(&sacc[q], (double)val);
  }
  {
    float val = tot;
#pragma unroll
    for (int o=16;o;o>>=1) val += __shfl_down_sync(0xffffffffu, val, o);
    if ((t & 31) == 0) atomicAdd(&sacc[22], (double)val);
  }
  __syncthreads();
  if (t < 23) atomicAdd(&g_acc[t], sacc[t]);
}

__global__ void k_final(float* __restrict__ out){
  int q = threadIdx.x;
  if (q < 22) out[q] = (float)(g_acc[q] / g_acc[22]);
}

extern "C" void kernel_launch(void* const* d_in, const int* in_sizes, int n_in,
                              void* d_out, int out_size)
{
  const float* params = (const float*)d_in[0];
  const float* sre    = (const float*)d_in[1];
  const float* sim    = (const float*)d_in[2];
  float* out = (float*)d_out;

  // Layer 1: A writes bufA (dir=1), B in-place on bufA (sel=1)
  k_passA<true ><<<1024,256>>>(params, sre, sim, 0, 1);
  k_passB<<<1024,256>>>(params, 0, 1);
  // Layer 2: bufA -> bufB (dir=0), B on bufB (sel=0)
  k_passA<false><<<1024,256>>>(params, nullptr, nullptr, 1, 0);
  k_passB<<<1024,256>>>(params, 1, 0);
  // Layer 3: bufB -> bufA
  k_passA<false><<<1024,256>>>(params, nullptr, nullptr, 2, 1);
  k_passB<<<1024,256>>>(params, 2, 1);
  // Layer 4: bufA -> bufB, B fuses final ladder + reduction
  k_passA<false><<<1024,256>>>(params, nullptr, nullptr, 3, 0);
  k_passB_last<<<1024,256>>>(params, 3, 0);

  k_final<<<1,32>>>(out);
}